// round 1
// baseline (speedup 1.0000x reference)
#include <cuda_runtime.h>
#include <cstdint>

#define EPS_BN 1e-5f

// Problem constants
#define BATCH   32
#define CIN     128
#define COUT    256
#define CEXP    1024
#define HOUT    28
#define HWOUT   784            // 28*28
#define MPIX    25088          // BATCH * HWOUT  (= 392 * 64 exactly)
#define K1      512            // CIN * 2 * 2

// ---------------- scratch (device globals; no allocation allowed) ----------
__device__ float g_A [(size_t)K1   * MPIX];   // im2col'd, k-major   (51.4 MB)
__device__ float g_t0[(size_t)BATCH * COUT * HWOUT];  // conv1 out, NCHW (25.7 MB)
__device__ float g_t1[(size_t)COUT * MPIX];   // dw+bn out, k-major   (25.7 MB)
__device__ float g_t2[(size_t)CEXP * MPIX];   // expand out, k-major (102.8 MB)
__device__ float g_Wd[K1 * COUT];             // quantized, k-major
__device__ float g_W1[COUT * 49];             // quantized, natural layout
__device__ float g_W2[COUT * CEXP];           // quantized, k-major [256][1024]
__device__ float g_W3[CEXP * COUT];           // quantized, k-major [1024][256]
__device__ unsigned g_max[4];

// ---------------- weight quantization (DoReFa, k=4) ------------------------
__global__ void init_max_kernel() {
    if (threadIdx.x < 4) g_max[threadIdx.x] = 0u;
}

__global__ void max_tanh_kernel(const float* __restrict__ w, int n, int slot) {
    float lm = 0.f;
    for (int i = blockIdx.x * blockDim.x + threadIdx.x; i < n;
         i += gridDim.x * blockDim.x)
        lm = fmaxf(lm, fabsf(tanhf(w[i])));
    #pragma unroll
    for (int o = 16; o > 0; o >>= 1)
        lm = fmaxf(lm, __shfl_xor_sync(0xffffffffu, lm, o));
    if ((threadIdx.x & 31) == 0)
        atomicMax(&g_max[slot], __float_as_uint(lm));   // vals >= 0: uint order ok
}

// quantize + transpose: src is [N][K] row-major, dst is [K][N].
// (Call with K=1 for no transpose.)
__global__ void quantW_kernel(const float* __restrict__ src, float* __restrict__ dst,
                              int N, int K, int slot) {
    int i = blockIdx.x * blockDim.x + threadIdx.x;
    if (i >= N * K) return;
    int n = i / K, k = i - n * K;
    float mx = __uint_as_float(g_max[slot]);
    float t  = tanhf(src[i]) / (2.f * mx) + 0.5f;
    float r  = rintf(t * 15.f);            // rint = round-half-even, matches jnp.round
    dst[k * N + n] = 2.f * (r / 15.f) - 1.f;
}

// ---------------- BN0 + act_quant16 + im2col (stride-2 2x2, no overlap) ----
__global__ void im2col_kernel(const float* __restrict__ x,
                              const float* __restrict__ bg, const float* __restrict__ bb,
                              const float* __restrict__ bm, const float* __restrict__ bv) {
    int m = blockIdx.x * 256 + threadIdx.x;        // gridDim.x = 98 -> exactly MPIX
    int k = blockIdx.y;                            // 0..511
    int c  = k >> 2;
    int dy = (k >> 1) & 1, dx = k & 1;
    int b  = m / HWOUT, s = m - b * HWOUT;
    int oh = s / HOUT,  ow = s - oh * HOUT;
    int ih = oh * 2 + dy, iw = ow * 2 + dx;
    float v    = x[(((size_t)b * CIN + c) * 56 + ih) * 56 + iw];
    float inv  = bg[c] / sqrtf(bv[c] + EPS_BN);
    float bias = bb[c] - bm[c] * inv;
    float y = v * inv + bias;
    y = fminf(fmaxf(y, 0.f), 1.f);
    y = rintf(y * 65535.f) / 65535.f;              // act_quant k=16
    g_A[(size_t)k * MPIX + m] = y;
}

// ---------------- tiled SGEMM: C[m,n] = sum_k At[k][m] * Bt[k][n] ----------
// MODE 0: write NCHW (conv1 -> t0)
// MODE 1: relu, write k-major [n][m] (expand -> t2)
// MODE 2: + resid(NCHW), clip, quant4, write NCHW (project -> out)
template<int MODE>
__global__ void sgemm_kernel(const float* __restrict__ At, const float* __restrict__ Bt,
                             float* __restrict__ out, int K, int N,
                             const float* __restrict__ resid) {
    __shared__ float As[16][64];
    __shared__ float Bs[16][64];
    const int tid = threadIdx.x;
    const int tx = tid & 15, ty = tid >> 4;
    const int m0 = blockIdx.x * 64, n0 = blockIdx.y * 64;
    const int lrow = tid >> 4;          // k within tile
    const int lcol = (tid & 15) * 4;    // col within tile

    float acc[4][4];
    #pragma unroll
    for (int i = 0; i < 4; i++)
        #pragma unroll
        for (int j = 0; j < 4; j++) acc[i][j] = 0.f;

    for (int k0 = 0; k0 < K; k0 += 16) {
        float4 a4 = *(const float4*)(At + (size_t)(k0 + lrow) * MPIX + m0 + lcol);
        float4 b4 = *(const float4*)(Bt + (size_t)(k0 + lrow) * N    + n0 + lcol);
        __syncthreads();
        *(float4*)&As[lrow][lcol] = a4;
        *(float4*)&Bs[lrow][lcol] = b4;
        __syncthreads();
        #pragma unroll
        for (int kk = 0; kk < 16; kk++) {
            float4 a = *(const float4*)&As[kk][tx * 4];
            float4 b = *(const float4*)&Bs[kk][ty * 4];
            float av[4] = {a.x, a.y, a.z, a.w};
            float bv[4] = {b.x, b.y, b.z, b.w};
            #pragma unroll
            for (int i = 0; i < 4; i++)
                #pragma unroll
                for (int j = 0; j < 4; j++)
                    acc[i][j] = fmaf(av[i], bv[j], acc[i][j]);
        }
    }

    #pragma unroll
    for (int i = 0; i < 4; i++) {
        int m = m0 + tx * 4 + i;
        int b = m / HWOUT, s = m - b * HWOUT;
        #pragma unroll
        for (int j = 0; j < 4; j++) {
            int n = n0 + ty * 4 + j;
            float v = acc[i][j];
            if (MODE == 0) {
                out[((size_t)b * COUT + n) * HWOUT + s] = v;
            } else if (MODE == 1) {
                out[(size_t)n * MPIX + m] = fmaxf(v, 0.f);
            } else {
                size_t idx = ((size_t)b * COUT + n) * HWOUT + s;
                v += resid[idx];
                v = fminf(fmaxf(v, 0.f), 1.f);
                out[idx] = rintf(v * 15.f) / 15.f;   // act_quant k=4
            }
        }
    }
}

// ---------------- depthwise 7x7 (pad 3) + BN1 ------------------------------
__global__ void dwconv_kernel(const float* __restrict__ bg, const float* __restrict__ bb,
                              const float* __restrict__ bm, const float* __restrict__ bv) {
    __shared__ float tile[34 * 34];
    __shared__ float w[49];
    int bc = blockIdx.x;            // b*COUT + c
    int c = bc & (COUT - 1);
    int b = bc >> 8;
    const float* plane = g_t0 + (size_t)bc * HWOUT;
    int tid = threadIdx.x;
    for (int idx = tid; idx < 34 * 34; idx += 256) {
        int r = idx / 34, cc = idx - r * 34;
        int ih = r - 3, iw = cc - 3;
        tile[idx] = (ih >= 0 && ih < HOUT && iw >= 0 && iw < HOUT)
                        ? plane[ih * HOUT + iw] : 0.f;
    }
    if (tid < 49) w[tid] = g_W1[c * 49 + tid];
    __syncthreads();
    float inv  = bg[c] / sqrtf(bv[c] + EPS_BN);
    float bias = bb[c] - bm[c] * inv;
    for (int s = tid; s < HWOUT; s += 256) {
        int oh = s / HOUT, ow = s - oh * HOUT;
        float sum = 0.f;
        #pragma unroll
        for (int i = 0; i < 7; i++)
            #pragma unroll
            for (int j = 0; j < 7; j++)
                sum = fmaf(tile[(oh + i) * 34 + ow + j], w[i * 7 + j], sum);
        g_t1[(size_t)c * MPIX + b * HWOUT + s] = sum * inv + bias;
    }
}

// ---------------- launch ----------------------------------------------------
extern "C" void kernel_launch(void* const* d_in, const int* in_sizes, int n_in,
                              void* d_out, int out_size) {
    const float* x     = (const float*)d_in[0];
    const float* bn0_g = (const float*)d_in[1];
    const float* bn0_b = (const float*)d_in[2];
    const float* bn0_m = (const float*)d_in[3];
    const float* bn0_v = (const float*)d_in[4];
    const float* Wd    = (const float*)d_in[5];
    const float* W1    = (const float*)d_in[6];
    const float* bn1_g = (const float*)d_in[7];
    const float* bn1_b = (const float*)d_in[8];
    const float* bn1_m = (const float*)d_in[9];
    const float* bn1_v = (const float*)d_in[10];
    const float* W2    = (const float*)d_in[11];
    const float* W3    = (const float*)d_in[12];
    float* out = (float*)d_out;

    void *pA, *pT0, *pT1, *pT2, *pWd, *pW1, *pW2, *pW3;
    cudaGetSymbolAddress(&pA,  g_A);
    cudaGetSymbolAddress(&pT0, g_t0);
    cudaGetSymbolAddress(&pT1, g_t1);
    cudaGetSymbolAddress(&pT2, g_t2);
    cudaGetSymbolAddress(&pWd, g_Wd);
    cudaGetSymbolAddress(&pW1, g_W1);
    cudaGetSymbolAddress(&pW2, g_W2);
    cudaGetSymbolAddress(&pW3, g_W3);

    // 1) weight quantization
    init_max_kernel<<<1, 32>>>();
    max_tanh_kernel<<<128, 256>>>(Wd, COUT * K1, 0);
    max_tanh_kernel<<<32, 256>>>(W1, COUT * 49, 1);
    max_tanh_kernel<<<128, 256>>>(W2, CEXP * COUT, 2);
    max_tanh_kernel<<<128, 256>>>(W3, COUT * CEXP, 3);
    quantW_kernel<<<(COUT * K1 + 255) / 256, 256>>>(Wd, (float*)pWd, COUT, K1, 0);
    quantW_kernel<<<(COUT * 49 + 255) / 256, 256>>>(W1, (float*)pW1, COUT * 49, 1, 1);
    quantW_kernel<<<(CEXP * COUT + 255) / 256, 256>>>(W2, (float*)pW2, CEXP, COUT, 2);
    quantW_kernel<<<(COUT * CEXP + 255) / 256, 256>>>(W3, (float*)pW3, COUT, CEXP, 3);

    // 2) BN0 + q16 + im2col
    im2col_kernel<<<dim3(98, K1), 256>>>(x, bn0_g, bn0_b, bn0_m, bn0_v);

    // 3) conv1 (stride-2 2x2) as GEMM -> t0 (NCHW)
    sgemm_kernel<0><<<dim3(MPIX / 64, COUT / 64), 256>>>(
        (const float*)pA, (const float*)pWd, (float*)pT0, K1, COUT, nullptr);

    // 4) depthwise 7x7 + BN1 -> t1 (k-major)
    dwconv_kernel<<<BATCH * COUT, 256>>>(bn1_g, bn1_b, bn1_m, bn1_v);

    // 5) 1x1 expand + ReLU -> t2 (k-major)
    sgemm_kernel<1><<<dim3(MPIX / 64, CEXP / 64), 256>>>(
        (const float*)pT1, (const float*)pW2, (float*)pT2, COUT, CEXP, nullptr);

    // 6) 1x1 project + residual + act_quant4 -> out (NCHW)
    sgemm_kernel<2><<<dim3(MPIX / 64, COUT / 64), 256>>>(
        (const float*)pT2, (const float*)pW3, out, CEXP, COUT, (const float*)pT0);
}

// round 2
// speedup vs baseline: 1.9521x; 1.9521x over previous
#include <cuda_runtime.h>
#include <cuda_bf16.h>
#include <cstdint>

#define EPS_BN 1e-5f

#define BATCH   32
#define CIN     128
#define COUT    256
#define CEXP    1024
#define HOUT    28
#define HWOUT   784
#define MPIX    25088          // BATCH*HWOUT, divisible by 128
#define KL1     512            // conv1 logical K (CIN*2*2)

// ------------- scratch (device globals) -------------------------------------
// packed activations: uint32 = (bf16 hi << 16) | bf16 lo
__device__ uint32_t g_A [(size_t)KL1  * MPIX];     // conv1 A, [KL1][M]
__device__ float    g_t0[(size_t)BATCH * COUT * HWOUT]; // conv1 out NCHW fp32
__device__ uint32_t g_t1[(size_t)COUT * MPIX];     // dw+bn out packed [COUT][M]
__device__ uint32_t g_t2[(size_t)CEXP * MPIX];     // expand out packed [CEXP][M]
__device__ __nv_bfloat16 g_Wd[2 * KL1  * COUT];    // 15*w, dup rows, [2KL][N]
__device__ float         g_W1f[COUT * 49];         // true quantized dw weights
__device__ __nv_bfloat16 g_W2[2 * COUT * CEXP];
__device__ __nv_bfloat16 g_W3[2 * CEXP * COUT];
__device__ unsigned g_max[4];

// ------------- helpers -------------------------------------------------------
__device__ __forceinline__ uint32_t pack_hl(float v) {
    __nv_bfloat16 h = __float2bfloat16(v);
    float r = v - __bfloat162float(h);
    __nv_bfloat16 l = __float2bfloat16(r);
    return ((uint32_t)__bfloat16_as_ushort(h) << 16) | (uint32_t)__bfloat16_as_ushort(l);
}

__device__ __forceinline__ void ldmx4t(uint32_t& r0, uint32_t& r1, uint32_t& r2,
                                       uint32_t& r3, uint32_t addr) {
    asm volatile("ldmatrix.sync.aligned.m8n8.x4.trans.shared.b16 {%0,%1,%2,%3},[%4];"
                 : "=r"(r0), "=r"(r1), "=r"(r2), "=r"(r3) : "r"(addr));
}

__device__ __forceinline__ void mma16816(float c[4], const uint32_t a[4],
                                         uint32_t b0, uint32_t b1) {
    asm volatile("mma.sync.aligned.m16n8k16.row.col.f32.bf16.bf16.f32 "
                 "{%0,%1,%2,%3},{%4,%5,%6,%7},{%8,%9},{%0,%1,%2,%3};"
                 : "+f"(c[0]), "+f"(c[1]), "+f"(c[2]), "+f"(c[3])
                 : "r"(a[0]), "r"(a[1]), "r"(a[2]), "r"(a[3]), "r"(b0), "r"(b1));
}

// ------------- weight quantization ------------------------------------------
__global__ void init_max_kernel() { if (threadIdx.x < 4) g_max[threadIdx.x] = 0u; }

__global__ void max_tanh_kernel(const float* __restrict__ w, int n, int slot) {
    float lm = 0.f;
    for (int i = blockIdx.x * blockDim.x + threadIdx.x; i < n;
         i += gridDim.x * blockDim.x)
        lm = fmaxf(lm, fabsf(tanhf(w[i])));
    #pragma unroll
    for (int o = 16; o > 0; o >>= 1)
        lm = fmaxf(lm, __shfl_xor_sync(0xffffffffu, lm, o));
    if ((threadIdx.x & 31) == 0) atomicMax(&g_max[slot], __float_as_uint(lm));
}

// scaled (15*w) bf16, transposed to [K][N] and duplicated onto rows 2k, 2k+1
__global__ void quantW_mma_kernel(const float* __restrict__ src, __nv_bfloat16* dst,
                                  int N, int K, int slot) {
    int i = blockIdx.x * blockDim.x + threadIdx.x;
    if (i >= N * K) return;
    int n = i / K, k = i - n * K;
    float mx = __uint_as_float(g_max[slot]);
    float t  = tanhf(src[i]) / (2.f * mx) + 0.5f;
    float r  = rintf(t * 15.f);
    __nv_bfloat16 v = __float2bfloat16(2.f * r - 15.f);   // odd integer, exact
    dst[(size_t)(2 * k) * N + n] = v;
    dst[(size_t)(2 * k + 1) * N + n] = v;
}

// true-valued fp32 quantized weights (depthwise)
__global__ void quantW_dw_kernel(const float* __restrict__ src, float* dst,
                                 int n, int slot) {
    int i = blockIdx.x * blockDim.x + threadIdx.x;
    if (i >= n) return;
    float mx = __uint_as_float(g_max[slot]);
    float t  = tanhf(src[i]) / (2.f * mx) + 0.5f;
    dst[i] = 2.f * (rintf(t * 15.f) / 15.f) - 1.f;
}

// ------------- BN0 + q16 + im2col -> packed hi/lo ---------------------------
__global__ void im2col_kernel(const float* __restrict__ x,
                              const float* __restrict__ bg, const float* __restrict__ bb,
                              const float* __restrict__ bm, const float* __restrict__ bv) {
    int m = blockIdx.x * 256 + threadIdx.x;
    int k = blockIdx.y;
    int c = k >> 2;
    int dy = (k >> 1) & 1, dx = k & 1;
    int b = m / HWOUT, s = m - b * HWOUT;
    int oh = s / HOUT, ow = s - oh * HOUT;
    float v    = x[(((size_t)b * CIN + c) * 56 + oh * 2 + dy) * 56 + ow * 2 + dx];
    float inv  = bg[c] / sqrtf(bv[c] + EPS_BN);
    float bias = bb[c] - bm[c] * inv;
    float y = fminf(fmaxf(v * inv + bias, 0.f), 1.f);
    y = rintf(y * 65535.f) / 65535.f;
    g_A[(size_t)k * MPIX + m] = pack_hl(y);
}

// ------------- tensor-core GEMM ---------------------------------------------
// C[m][n] = (1/15) * sum_k unpack(Ap[k][m]) . B[2k..2k+1][n]
// MODE 0: write fp32 NCHW       (conv1)
// MODE 1: relu -> packed [n][M] (expand)
// MODE 2: +resid NCHW, clip, q4 -> fp32 NCHW (project)
#define BM 128
#define BN 128
#define BKL 16
#define BK 32
#define LDSA 136   // elems, 272B row stride (16B-aligned, conflict-free ldmatrix)

template<int MODE>
__global__ void __launch_bounds__(256)
mma_gemm(const uint32_t* __restrict__ Ap, const __nv_bfloat16* __restrict__ Bw,
         int KL, int N, float* __restrict__ outf, uint32_t* __restrict__ outp,
         const float* __restrict__ resid) {
    __shared__ __nv_bfloat16 As[BK][LDSA];
    __shared__ __nv_bfloat16 Bs[BK][LDSA];
    const int tid = threadIdx.x;
    const int lane = tid & 31, wid = tid >> 5;
    const int m0b = blockIdx.x * BM, n0b = blockIdx.y * BN;
    const int wm = (wid & 1) * 64;
    const int wn = (wid >> 1) * 32;

    float acc[4][4][4];
    #pragma unroll
    for (int t = 0; t < 4; t++)
        #pragma unroll
        for (int u = 0; u < 4; u++)
            #pragma unroll
            for (int e = 0; e < 4; e++) acc[t][u][e] = 0.f;

    // global load mapping
    const int arow = tid >> 5;        // 0..7 (+8)
    const int achk = tid & 31;        // 4 packed elems each
    const int brow = tid >> 4;        // 0..15 (+16)
    const int bchk = tid & 15;        // 8 bf16 each

    // ldmatrix per-thread addresses
    const uint32_t asb = (uint32_t)__cvta_generic_to_shared(&As[0][0]);
    const uint32_t bsb = (uint32_t)__cvta_generic_to_shared(&Bs[0][0]);
    const int g = lane >> 3, r = lane & 7;
    const int a_row0 = ((g >> 1) << 3) + r;
    const int a_col  = wm + ((g & 1) << 3);
    const int b_row0 = ((g & 1) << 3) + r;
    const int b_col0 = wn + ((g >> 1) << 3);

    const int iters = KL / BKL;
    for (int it = 0; it < iters; ++it) {
        const int kp = it * BKL;   // packed rows
        const int kb = it * BK;    // bf16 rows
        uint4 va0 = *(const uint4*)(Ap + (size_t)(kp + arow) * MPIX + m0b + achk * 4);
        uint4 va1 = *(const uint4*)(Ap + (size_t)(kp + arow + 8) * MPIX + m0b + achk * 4);
        uint4 vb0 = *(const uint4*)(Bw + (size_t)(kb + brow) * N + n0b + bchk * 8);
        uint4 vb1 = *(const uint4*)(Bw + (size_t)(kb + brow + 16) * N + n0b + bchk * 8);
        __syncthreads();
        // unpack A: hi -> row 2r, lo -> row 2r+1
        *(uint2*)&As[2 * arow][achk * 4] =
            make_uint2(__byte_perm(va0.x, va0.y, 0x7632), __byte_perm(va0.z, va0.w, 0x7632));
        *(uint2*)&As[2 * arow + 1][achk * 4] =
            make_uint2(__byte_perm(va0.x, va0.y, 0x5410), __byte_perm(va0.z, va0.w, 0x5410));
        *(uint2*)&As[2 * (arow + 8)][achk * 4] =
            make_uint2(__byte_perm(va1.x, va1.y, 0x7632), __byte_perm(va1.z, va1.w, 0x7632));
        *(uint2*)&As[2 * (arow + 8) + 1][achk * 4] =
            make_uint2(__byte_perm(va1.x, va1.y, 0x5410), __byte_perm(va1.z, va1.w, 0x5410));
        *(uint4*)&Bs[brow][bchk * 8] = vb0;
        *(uint4*)&Bs[brow + 16][bchk * 8] = vb1;
        __syncthreads();

        #pragma unroll
        for (int h = 0; h < 2; ++h) {
            uint32_t af[4][4];
            #pragma unroll
            for (int t = 0; t < 4; ++t)
                ldmx4t(af[t][0], af[t][1], af[t][2], af[t][3],
                       asb + ((a_row0 + h * 16) * LDSA + a_col + t * 16) * 2);
            uint32_t bfr[2][4];
            #pragma unroll
            for (int p = 0; p < 2; ++p)
                ldmx4t(bfr[p][0], bfr[p][1], bfr[p][2], bfr[p][3],
                       bsb + ((b_row0 + h * 16) * LDSA + b_col0 + p * 16) * 2);
            #pragma unroll
            for (int t = 0; t < 4; ++t)
                #pragma unroll
                for (int u = 0; u < 4; ++u)
                    mma16816(acc[t][u], af[t],
                             bfr[u >> 1][(u & 1) * 2], bfr[u >> 1][(u & 1) * 2 + 1]);
        }
    }

    // epilogue
    const float SC = 1.f / 15.f;
    const int row_ = lane >> 2, col_ = (lane & 3) * 2;
    #pragma unroll
    for (int t = 0; t < 4; ++t) {
        #pragma unroll
        for (int u = 0; u < 4; ++u) {
            #pragma unroll
            for (int e = 0; e < 4; ++e) {
                int m = m0b + wm + t * 16 + row_ + ((e >> 1) ? 8 : 0);
                int n = n0b + wn + u * 8 + col_ + (e & 1);
                float v = acc[t][u][e] * SC;
                if (MODE == 0) {
                    int b = m / HWOUT, s = m - b * HWOUT;
                    outf[((size_t)b * COUT + n) * HWOUT + s] = v;
                } else if (MODE == 1) {
                    outp[(size_t)n * MPIX + m] = pack_hl(fmaxf(v, 0.f));
                } else {
                    int b = m / HWOUT, s = m - b * HWOUT;
                    size_t idx = ((size_t)b * COUT + n) * HWOUT + s;
                    v += resid[idx];
                    v = fminf(fmaxf(v, 0.f), 1.f);
                    outf[idx] = rintf(v * 15.f) * SC;
                }
            }
        }
    }
}

// ------------- depthwise 7x7 + BN1 -> packed --------------------------------
__global__ void dwconv_kernel(const float* __restrict__ bg, const float* __restrict__ bb,
                              const float* __restrict__ bm, const float* __restrict__ bv) {
    __shared__ float tile[34 * 34];
    __shared__ float w[49];
    int bc = blockIdx.x;
    int c = bc & (COUT - 1);
    int b = bc >> 8;
    const float* plane = g_t0 + (size_t)bc * HWOUT;
    int tid = threadIdx.x;
    for (int idx = tid; idx < 34 * 34; idx += 256) {
        int rr = idx / 34, cc = idx - rr * 34;
        int ih = rr - 3, iw = cc - 3;
        tile[idx] = (ih >= 0 && ih < HOUT && iw >= 0 && iw < HOUT)
                        ? plane[ih * HOUT + iw] : 0.f;
    }
    if (tid < 49) w[tid] = g_W1f[c * 49 + tid];
    __syncthreads();
    float inv  = bg[c] / sqrtf(bv[c] + EPS_BN);
    float bias = bb[c] - bm[c] * inv;
    for (int s = tid; s < HWOUT; s += 256) {
        int oh = s / HOUT, ow = s - oh * HOUT;
        float sum = 0.f;
        #pragma unroll
        for (int i = 0; i < 7; i++)
            #pragma unroll
            for (int j = 0; j < 7; j++)
                sum = fmaf(tile[(oh + i) * 34 + ow + j], w[i * 7 + j], sum);
        g_t1[(size_t)c * MPIX + b * HWOUT + s] = pack_hl(sum * inv + bias);
    }
}

// ------------- launch --------------------------------------------------------
extern "C" void kernel_launch(void* const* d_in, const int* in_sizes, int n_in,
                              void* d_out, int out_size) {
    const float* x     = (const float*)d_in[0];
    const float* bn0_g = (const float*)d_in[1];
    const float* bn0_b = (const float*)d_in[2];
    const float* bn0_m = (const float*)d_in[3];
    const float* bn0_v = (const float*)d_in[4];
    const float* Wd    = (const float*)d_in[5];
    const float* W1    = (const float*)d_in[6];
    const float* bn1_g = (const float*)d_in[7];
    const float* bn1_b = (const float*)d_in[8];
    const float* bn1_m = (const float*)d_in[9];
    const float* bn1_v = (const float*)d_in[10];
    const float* W2    = (const float*)d_in[11];
    const float* W3    = (const float*)d_in[12];
    float* out = (float*)d_out;

    void *pA, *pT0, *pT1, *pT2, *pWd, *pW1, *pW2, *pW3;
    cudaGetSymbolAddress(&pA,  g_A);
    cudaGetSymbolAddress(&pT0, g_t0);
    cudaGetSymbolAddress(&pT1, g_t1);
    cudaGetSymbolAddress(&pT2, g_t2);
    cudaGetSymbolAddress(&pWd, g_Wd);
    cudaGetSymbolAddress(&pW1, g_W1f);
    cudaGetSymbolAddress(&pW2, g_W2);
    cudaGetSymbolAddress(&pW3, g_W3);

    // weight quantization
    init_max_kernel<<<1, 32>>>();
    max_tanh_kernel<<<128, 256>>>(Wd, COUT * KL1, 0);
    max_tanh_kernel<<<32, 256>>>(W1, COUT * 49, 1);
    max_tanh_kernel<<<128, 256>>>(W2, CEXP * COUT, 2);
    max_tanh_kernel<<<128, 256>>>(W3, COUT * CEXP, 3);
    quantW_mma_kernel<<<(COUT * KL1 + 255) / 256, 256>>>(Wd, (__nv_bfloat16*)pWd, COUT, KL1, 0);
    quantW_dw_kernel<<<(COUT * 49 + 255) / 256, 256>>>(W1, (float*)pW1, COUT * 49, 1);
    quantW_mma_kernel<<<(CEXP * COUT + 255) / 256, 256>>>(W2, (__nv_bfloat16*)pW2, CEXP, COUT, 2);
    quantW_mma_kernel<<<(COUT * CEXP + 255) / 256, 256>>>(W3, (__nv_bfloat16*)pW3, COUT, CEXP, 3);

    // BN0 + q16 + im2col (packed hi/lo)
    im2col_kernel<<<dim3(98, KL1), 256>>>(x, bn0_g, bn0_b, bn0_m, bn0_v);

    // conv1: M=25088, N=256, KL=512
    mma_gemm<0><<<dim3(MPIX / BM, COUT / BN), 256>>>(
        (const uint32_t*)pA, (const __nv_bfloat16*)pWd, KL1, COUT,
        (float*)pT0, nullptr, nullptr);

    // depthwise + BN1
    dwconv_kernel<<<BATCH * COUT, 256>>>(bn1_g, bn1_b, bn1_m, bn1_v);

    // expand: N=1024, KL=256
    mma_gemm<1><<<dim3(MPIX / BM, CEXP / BN), 256>>>(
        (const uint32_t*)pT1, (const __nv_bfloat16*)pW2, COUT, CEXP,
        nullptr, (uint32_t*)pT2, nullptr);

    // project: N=256, KL=1024, + residual + q4
    mma_gemm<2><<<dim3(MPIX / BM, COUT / BN), 256>>>(
        (const uint32_t*)pT2, (const __nv_bfloat16*)pW3, CEXP, COUT,
        out, nullptr, (const float*)pT0);
}

// round 4
// speedup vs baseline: 2.3261x; 1.1916x over previous
#include <cuda_runtime.h>
#include <cuda_bf16.h>
#include <cstdint>

#define EPS_BN 1e-5f

#define BATCH   32
#define CIN     128
#define COUT    256
#define CEXP    1024
#define HOUT    28
#define HWOUT   784
#define MPIX    25088          // BATCH*HWOUT, divisible by 128
#define KL1     512            // conv1 logical K (CIN*2*2)

// ------------- scratch (device globals) -------------------------------------
// split activations: row 2k = bf16 hi, row 2k+1 = bf16 lo of logical k-row
__device__ __nv_bfloat16 g_A [(size_t)2 * KL1  * MPIX];   // conv1 A   (51.4 MB)
__device__ float         g_t0[(size_t)BATCH * COUT * HWOUT]; // conv1 out NCHW
__device__ __nv_bfloat16 g_t1[(size_t)2 * COUT * MPIX];   // dw out    (25.7 MB)
__device__ __nv_bfloat16 g_t2[(size_t)2 * CEXP * MPIX];   // expand out(102.8 MB)
__device__ __nv_bfloat16 g_Wd[2 * KL1  * COUT];           // 15*w, dup rows
__device__ float         g_W1f[COUT * 49];
__device__ __nv_bfloat16 g_W2[2 * COUT * CEXP];
__device__ __nv_bfloat16 g_W3[2 * CEXP * COUT];
__device__ unsigned g_max[4];

// ------------- helpers -------------------------------------------------------
__device__ __forceinline__ void ldmx4t(uint32_t& r0, uint32_t& r1, uint32_t& r2,
                                       uint32_t& r3, uint32_t addr) {
    asm volatile("ldmatrix.sync.aligned.m8n8.x4.trans.shared.b16 {%0,%1,%2,%3},[%4];"
                 : "=r"(r0), "=r"(r1), "=r"(r2), "=r"(r3) : "r"(addr));
}

__device__ __forceinline__ void mma16816(float c[4], const uint32_t a[4],
                                         uint32_t b0, uint32_t b1) {
    asm volatile("mma.sync.aligned.m16n8k16.row.col.f32.bf16.bf16.f32 "
                 "{%0,%1,%2,%3},{%4,%5,%6,%7},{%8,%9},{%0,%1,%2,%3};"
                 : "+f"(c[0]), "+f"(c[1]), "+f"(c[2]), "+f"(c[3])
                 : "r"(a[0]), "r"(a[1]), "r"(a[2]), "r"(a[3]), "r"(b0), "r"(b1));
}

__device__ __forceinline__ void cp16(uint32_t s, const void* g) {
    asm volatile("cp.async.cg.shared.global [%0],[%1],16;\n" :: "r"(s), "l"(g));
}
__device__ __forceinline__ void cp_commit() {
    asm volatile("cp.async.commit_group;\n");
}

// ------------- weight quantization (fused) -----------------------------------
__global__ void init_max_kernel() { if (threadIdx.x < 4) g_max[threadIdx.x] = 0u; }

__global__ void max4_kernel(const float* __restrict__ w0, const float* __restrict__ w1,
                            const float* __restrict__ w2, const float* __restrict__ w3) {
    int slot = blockIdx.y;
    const float* w; int n;
    if      (slot == 0) { w = w0; n = COUT * KL1; }
    else if (slot == 1) { w = w1; n = COUT * 49; }
    else if (slot == 2) { w = w2; n = CEXP * COUT; }
    else                { w = w3; n = COUT * CEXP; }
    float lm = 0.f;
    for (int i = blockIdx.x * blockDim.x + threadIdx.x; i < n;
         i += gridDim.x * blockDim.x)
        lm = fmaxf(lm, fabsf(tanhf(w[i])));
    #pragma unroll
    for (int o = 16; o > 0; o >>= 1)
        lm = fmaxf(lm, __shfl_xor_sync(0xffffffffu, lm, o));
    if ((threadIdx.x & 31) == 0) atomicMax(&g_max[slot], __float_as_uint(lm));
}

// one kernel quantizes Wd/W2/W3 (scaled 15*w bf16, [2K][N] dup rows)
__global__ void quantW_all(const float* __restrict__ Wd, const float* __restrict__ W2,
                           const float* __restrict__ W3) {
    int which = blockIdx.y;
    const float* src; __nv_bfloat16* dst; int N, K, slot;
    if      (which == 0) { src = Wd; dst = g_Wd; N = COUT; K = KL1;  slot = 0; }
    else if (which == 1) { src = W2; dst = g_W2; N = CEXP; K = COUT; slot = 2; }
    else                 { src = W3; dst = g_W3; N = COUT; K = CEXP; slot = 3; }
    int i = blockIdx.x * 256 + threadIdx.x;
    if (i >= N * K) return;
    int n = i / K, k = i - n * K;
    float mx = __uint_as_float(g_max[slot]);
    float t  = tanhf(src[i]) / (2.f * mx) + 0.5f;
    float r  = rintf(t * 15.f);
    __nv_bfloat16 v = __float2bfloat16(2.f * r - 15.f);   // odd integer, exact
    dst[(size_t)(2 * k) * N + n] = v;
    dst[(size_t)(2 * k + 1) * N + n] = v;
}

__global__ void quantW_dw_kernel(const float* __restrict__ src) {
    int i = blockIdx.x * blockDim.x + threadIdx.x;
    if (i >= COUT * 49) return;
    float mx = __uint_as_float(g_max[1]);
    float t  = tanhf(src[i]) / (2.f * mx) + 0.5f;
    g_W1f[i] = 2.f * (rintf(t * 15.f) / 15.f) - 1.f;
}

// ------------- BN0 + q16 + im2col -> split bf16 rows -------------------------
__global__ void im2col_kernel(const float* __restrict__ x,
                              const float* __restrict__ bg, const float* __restrict__ bb,
                              const float* __restrict__ bm, const float* __restrict__ bv) {
    int m = blockIdx.x * 256 + threadIdx.x;
    int k = blockIdx.y;
    int c = k >> 2;
    int dy = (k >> 1) & 1, dx = k & 1;
    int b = m / HWOUT, s = m - b * HWOUT;
    int oh = s / HOUT, ow = s - oh * HOUT;
    float v    = x[(((size_t)b * CIN + c) * 56 + oh * 2 + dy) * 56 + ow * 2 + dx];
    float inv  = bg[c] / sqrtf(bv[c] + EPS_BN);
    float bias = bb[c] - bm[c] * inv;
    float y = fminf(fmaxf(v * inv + bias, 0.f), 1.f);
    y = rintf(y * 65535.f) / 65535.f;
    __nv_bfloat16 h = __float2bfloat16(y);
    g_A[(size_t)(2 * k) * MPIX + m]     = h;
    g_A[(size_t)(2 * k + 1) * MPIX + m] = __float2bfloat16(y - __bfloat162float(h));
}

// ------------- tensor-core GEMM, cp.async double-buffered --------------------
// C[m][n] = (1/15) * sum_{k'} A[k'][m] * B[k'][n],  Kp = k' rows
// MODE 0: write fp32 NCHW        (conv1)
// MODE 1: relu -> split bf16 [2n][M] (expand)
// MODE 2: +resid NCHW, clip, q4 -> fp32 NCHW (project)
#define BM 128
#define BN 128
#define BK 32
#define LDS 136   // bf16 elems; 272B row stride, 16B-aligned, ldmatrix conflict-free

template<int MODE>
__global__ void __launch_bounds__(256)
mma_gemm(const __nv_bfloat16* __restrict__ A, const __nv_bfloat16* __restrict__ B,
         int Kp, int N, float* __restrict__ outf, __nv_bfloat16* __restrict__ outp,
         const float* __restrict__ resid) {
    __shared__ __nv_bfloat16 As[2][BK][LDS];
    __shared__ __nv_bfloat16 Bs[2][BK][LDS];
    const int tid = threadIdx.x;
    const int lane = tid & 31, wid = tid >> 5;
    const int m0b = blockIdx.x * BM, n0b = blockIdx.y * BN;
    const int wm = (wid & 1) * 64;
    const int wn = (wid >> 1) * 32;

    float acc[4][4][4];
    #pragma unroll
    for (int t = 0; t < 4; t++)
        #pragma unroll
        for (int u = 0; u < 4; u++)
            #pragma unroll
            for (int e = 0; e < 4; e++) acc[t][u][e] = 0.f;

    // global->shared mapping: each thread two 16B chunks per tile per matrix
    const int r0 = tid >> 4;          // rows 0..15, +16
    const int c0 = (tid & 15) * 8;    // bf16 col

    const uint32_t asb = (uint32_t)__cvta_generic_to_shared(&As[0][0][0]);
    const uint32_t bsb = (uint32_t)__cvta_generic_to_shared(&Bs[0][0][0]);
    const uint32_t bufstride = BK * LDS * 2;   // bytes per buffer
    const uint32_t as_st = asb + (r0 * LDS + c0) * 2;
    const uint32_t bs_st = bsb + (r0 * LDS + c0) * 2;

    // ldmatrix per-thread addresses
    const int g = lane >> 3, r = lane & 7;
    const int a_row0 = ((g >> 1) << 3) + r;
    const int a_col  = wm + ((g & 1) << 3);
    const int b_row0 = ((g & 1) << 3) + r;
    const int b_col0 = wn + ((g >> 1) << 3);

    const int iters = Kp / BK;

    // prefetch tile 0
    {
        const __nv_bfloat16* ag = A + (size_t)r0 * MPIX + m0b + c0;
        const __nv_bfloat16* bg = B + (size_t)r0 * N + n0b + c0;
        cp16(as_st, ag);
        cp16(as_st + 16 * LDS * 2, ag + (size_t)16 * MPIX);
        cp16(bs_st, bg);
        cp16(bs_st + 16 * LDS * 2, bg + (size_t)16 * N);
        cp_commit();
    }

    for (int it = 0; it < iters; ++it) {
        const int p = it & 1;
        if (it + 1 < iters) {
            const int kb = (it + 1) * BK;
            const __nv_bfloat16* ag = A + (size_t)(kb + r0) * MPIX + m0b + c0;
            const __nv_bfloat16* bg = B + (size_t)(kb + r0) * N + n0b + c0;
            const uint32_t off = (p ^ 1) * bufstride;
            cp16(as_st + off, ag);
            cp16(as_st + off + 16 * LDS * 2, ag + (size_t)16 * MPIX);
            cp16(bs_st + off, bg);
            cp16(bs_st + off + 16 * LDS * 2, bg + (size_t)16 * N);
            cp_commit();
            asm volatile("cp.async.wait_group 1;\n");
        } else {
            asm volatile("cp.async.wait_group 0;\n");
        }
        __syncthreads();

        const uint32_t ab = asb + p * bufstride;
        const uint32_t bb = bsb + p * bufstride;
        #pragma unroll
        for (int h = 0; h < 2; ++h) {
            uint32_t af[4][4];
            #pragma unroll
            for (int t = 0; t < 4; ++t)
                ldmx4t(af[t][0], af[t][1], af[t][2], af[t][3],
                       ab + ((a_row0 + h * 16) * LDS + a_col + t * 16) * 2);
            uint32_t bfr[2][4];
            #pragma unroll
            for (int pq = 0; pq < 2; ++pq)
                ldmx4t(bfr[pq][0], bfr[pq][1], bfr[pq][2], bfr[pq][3],
                       bb + ((b_row0 + h * 16) * LDS + b_col0 + pq * 16) * 2);
            #pragma unroll
            for (int t = 0; t < 4; ++t)
                #pragma unroll
                for (int u = 0; u < 4; ++u)
                    mma16816(acc[t][u], af[t],
                             bfr[u >> 1][(u & 1) * 2], bfr[u >> 1][(u & 1) * 2 + 1]);
        }
        __syncthreads();
    }

    // epilogue
    const float SC = 1.f / 15.f;
    const int row_ = lane >> 2, col_ = (lane & 3) * 2;
    #pragma unroll
    for (int t = 0; t < 4; ++t) {
        #pragma unroll
        for (int u = 0; u < 4; ++u) {
            #pragma unroll
            for (int e = 0; e < 4; ++e) {
                int m = m0b + wm + t * 16 + row_ + ((e >> 1) ? 8 : 0);
                int n = n0b + wn + u * 8 + col_ + (e & 1);
                float v = acc[t][u][e] * SC;
                if (MODE == 0) {
                    int b = m / HWOUT, s = m - b * HWOUT;
                    outf[((size_t)b * COUT + n) * HWOUT + s] = v;
                } else if (MODE == 1) {
                    float vr = fmaxf(v, 0.f);
                    __nv_bfloat16 h = __float2bfloat16(vr);
                    outp[(size_t)(2 * n) * MPIX + m] = h;
                    outp[(size_t)(2 * n + 1) * MPIX + m] =
                        __float2bfloat16(vr - __bfloat162float(h));
                } else {
                    int b = m / HWOUT, s = m - b * HWOUT;
                    size_t idx = ((size_t)b * COUT + n) * HWOUT + s;
                    v += resid[idx];
                    v = fminf(fmaxf(v, 0.f), 1.f);
                    outf[idx] = rintf(v * 15.f) * SC;
                }
            }
        }
    }
}

// ------------- depthwise 7x7 + BN1 -> split bf16 -----------------------------
__global__ void dwconv_kernel(const float* __restrict__ bg, const float* __restrict__ bb,
                              const float* __restrict__ bm, const float* __restrict__ bv) {
    __shared__ float tile[34 * 34];
    __shared__ float w[49];
    int bc = blockIdx.x;
    int c = bc & (COUT - 1);
    int b = bc >> 8;
    const float* plane = g_t0 + (size_t)bc * HWOUT;
    int tid = threadIdx.x;
    for (int idx = tid; idx < 34 * 34; idx += 256) {
        int rr = idx / 34, cc = idx - rr * 34;
        int ih = rr - 3, iw = cc - 3;
        tile[idx] = (ih >= 0 && ih < HOUT && iw >= 0 && iw < HOUT)
                        ? plane[ih * HOUT + iw] : 0.f;
    }
    if (tid < 49) w[tid] = g_W1f[c * 49 + tid];
    __syncthreads();
    float inv  = bg[c] / sqrtf(bv[c] + EPS_BN);
    float bias = bb[c] - bm[c] * inv;
    for (int s = tid; s < HWOUT; s += 256) {
        int oh = s / HOUT, ow = s - oh * HOUT;
        float sum = 0.f;
        #pragma unroll
        for (int i = 0; i < 7; i++)
            #pragma unroll
            for (int j = 0; j < 7; j++)
                sum = fmaf(tile[(oh + i) * 34 + ow + j], w[i * 7 + j], sum);
        float y = sum * inv + bias;
        __nv_bfloat16 h = __float2bfloat16(y);
        int m = b * HWOUT + s;
        g_t1[(size_t)(2 * c) * MPIX + m]     = h;
        g_t1[(size_t)(2 * c + 1) * MPIX + m] = __float2bfloat16(y - __bfloat162float(h));
    }
}

// ------------- launch --------------------------------------------------------
extern "C" void kernel_launch(void* const* d_in, const int* in_sizes, int n_in,
                              void* d_out, int out_size) {
    const float* x     = (const float*)d_in[0];
    const float* bn0_g = (const float*)d_in[1];
    const float* bn0_b = (const float*)d_in[2];
    const float* bn0_m = (const float*)d_in[3];
    const float* bn0_v = (const float*)d_in[4];
    const float* Wd    = (const float*)d_in[5];
    const float* W1    = (const float*)d_in[6];
    const float* bn1_g = (const float*)d_in[7];
    const float* bn1_b = (const float*)d_in[8];
    const float* bn1_m = (const float*)d_in[9];
    const float* bn1_v = (const float*)d_in[10];
    const float* W2    = (const float*)d_in[11];
    const float* W3    = (const float*)d_in[12];
    float* out = (float*)d_out;

    void *pA, *pT0, *pT1, *pT2, *pWd, *pW2, *pW3;
    cudaGetSymbolAddress(&pA,  g_A);
    cudaGetSymbolAddress(&pT0, g_t0);
    cudaGetSymbolAddress(&pT1, g_t1);
    cudaGetSymbolAddress(&pT2, g_t2);
    cudaGetSymbolAddress(&pWd, g_Wd);
    cudaGetSymbolAddress(&pW2, g_W2);
    cudaGetSymbolAddress(&pW3, g_W3);

    // weight quantization (fused launches)
    init_max_kernel<<<1, 32>>>();
    max4_kernel<<<dim3(64, 4), 256>>>(Wd, W1, W2, W3);
    quantW_all<<<dim3(1024, 3), 256>>>(Wd, W2, W3);
    quantW_dw_kernel<<<(COUT * 49 + 255) / 256, 256>>>(W1);

    // BN0 + q16 + im2col (split bf16)
    im2col_kernel<<<dim3(98, KL1), 256>>>(x, bn0_g, bn0_b, bn0_m, bn0_v);

    // conv1: M=25088, N=256, Kp=1024
    mma_gemm<0><<<dim3(MPIX / BM, COUT / BN), 256>>>(
        (const __nv_bfloat16*)pA, (const __nv_bfloat16*)pWd, 2 * KL1, COUT,
        (float*)pT0, nullptr, nullptr);

    // depthwise + BN1
    dwconv_kernel<<<BATCH * COUT, 256>>>(bn1_g, bn1_b, bn1_m, bn1_v);

    // expand: N=1024, Kp=512
    mma_gemm<1><<<dim3(MPIX / BM, CEXP / BN), 256>>>(
        (const __nv_bfloat16*)pT1, (const __nv_bfloat16*)pW2, 2 * COUT, CEXP,
        nullptr, (__nv_bfloat16*)pT2, nullptr);

    // project: N=256, Kp=2048, + residual + q4
    mma_gemm<2><<<dim3(MPIX / BM, COUT / BN), 256>>>(
        (const __nv_bfloat16*)pT2, (const __nv_bfloat16*)pW3, 2 * CEXP, COUT,
        out, nullptr, (const float*)pT0);
}

// round 6
// speedup vs baseline: 2.4277x; 1.0437x over previous
#include <cuda_runtime.h>
#include <cuda_bf16.h>
#include <cstdint>

#define EPS_BN 1e-5f

#define BATCH   32
#define CIN     128
#define COUT    256
#define CEXP    1024
#define HOUT    28
#define HWOUT   784
#define MPIX    25088          // BATCH*HWOUT, divisible by 128
#define KL1     512            // conv1 logical K (CIN*2*2)

// ------------- scratch (device globals) -------------------------------------
// split activations: row 2k = bf16 hi, row 2k+1 = bf16 lo of logical k-row
__device__ __nv_bfloat16 g_A [(size_t)2 * KL1  * MPIX];   // conv1 A   (51.4 MB)
__device__ float         g_t0[(size_t)BATCH * COUT * HWOUT]; // conv1 out NCHW
__device__ __nv_bfloat16 g_t1[(size_t)2 * COUT * MPIX];   // dw out    (25.7 MB)
__device__ __nv_bfloat16 g_t2[(size_t)2 * CEXP * MPIX];   // expand out(102.8 MB)
__device__ __nv_bfloat16 g_Wd[2 * KL1  * COUT];           // 15*w, dup rows
__device__ float         g_W1f[COUT * 49];
__device__ __nv_bfloat16 g_W2[2 * COUT * CEXP];
__device__ __nv_bfloat16 g_W3[2 * CEXP * COUT];
__device__ unsigned g_max[4];

// ------------- helpers -------------------------------------------------------
__device__ __forceinline__ void ldmx4t(uint32_t& r0, uint32_t& r1, uint32_t& r2,
                                       uint32_t& r3, uint32_t addr) {
    asm volatile("ldmatrix.sync.aligned.m8n8.x4.trans.shared.b16 {%0,%1,%2,%3},[%4];"
                 : "=r"(r0), "=r"(r1), "=r"(r2), "=r"(r3) : "r"(addr));
}

__device__ __forceinline__ void mma16816(float c[4], const uint32_t a[4],
                                         uint32_t b0, uint32_t b1) {
    asm volatile("mma.sync.aligned.m16n8k16.row.col.f32.bf16.bf16.f32 "
                 "{%0,%1,%2,%3},{%4,%5,%6,%7},{%8,%9},{%0,%1,%2,%3};"
                 : "+f"(c[0]), "+f"(c[1]), "+f"(c[2]), "+f"(c[3])
                 : "r"(a[0]), "r"(a[1]), "r"(a[2]), "r"(a[3]), "r"(b0), "r"(b1));
}

__device__ __forceinline__ void cp16(uint32_t s, const void* g) {
    asm volatile("cp.async.cg.shared.global [%0],[%1],16;\n" :: "r"(s), "l"(g));
}
#define CP_COMMIT() asm volatile("cp.async.commit_group;\n")

// ------------- weight quantization (fused) -----------------------------------
__global__ void init_max_kernel() { if (threadIdx.x < 4) g_max[threadIdx.x] = 0u; }

__global__ void max4_kernel(const float* __restrict__ w0, const float* __restrict__ w1,
                            const float* __restrict__ w2, const float* __restrict__ w3) {
    int slot = blockIdx.y;
    const float* w; int n;
    if      (slot == 0) { w = w0; n = COUT * KL1; }
    else if (slot == 1) { w = w1; n = COUT * 49; }
    else if (slot == 2) { w = w2; n = CEXP * COUT; }
    else                { w = w3; n = COUT * CEXP; }
    float lm = 0.f;
    for (int i = blockIdx.x * blockDim.x + threadIdx.x; i < n;
         i += gridDim.x * blockDim.x)
        lm = fmaxf(lm, fabsf(tanhf(w[i])));
    #pragma unroll
    for (int o = 16; o > 0; o >>= 1)
        lm = fmaxf(lm, __shfl_xor_sync(0xffffffffu, lm, o));
    if ((threadIdx.x & 31) == 0) atomicMax(&g_max[slot], __float_as_uint(lm));
}

// one kernel quantizes Wd/W2/W3 (scaled 15*w bf16, [2K][N] dup rows)
__global__ void quantW_all(const float* __restrict__ Wd, const float* __restrict__ W2,
                           const float* __restrict__ W3) {
    int which = blockIdx.y;
    const float* src; __nv_bfloat16* dst; int N, K, slot;
    if      (which == 0) { src = Wd; dst = g_Wd; N = COUT; K = KL1;  slot = 0; }
    else if (which == 1) { src = W2; dst = g_W2; N = CEXP; K = COUT; slot = 2; }
    else                 { src = W3; dst = g_W3; N = COUT; K = CEXP; slot = 3; }
    int i = blockIdx.x * 256 + threadIdx.x;
    if (i >= N * K) return;
    int n = i / K, k = i - n * K;
    float mx = __uint_as_float(g_max[slot]);
    float t  = tanhf(src[i]) / (2.f * mx) + 0.5f;
    float r  = rintf(t * 15.f);
    __nv_bfloat16 v = __float2bfloat16(2.f * r - 15.f);   // odd integer, exact
    dst[(size_t)(2 * k) * N + n] = v;
    dst[(size_t)(2 * k + 1) * N + n] = v;
}

__global__ void quantW_dw_kernel(const float* __restrict__ src) {
    int i = blockIdx.x * blockDim.x + threadIdx.x;
    if (i >= COUT * 49) return;
    float mx = __uint_as_float(g_max[1]);
    float t  = tanhf(src[i]) / (2.f * mx) + 0.5f;
    g_W1f[i] = 2.f * (rintf(t * 15.f) / 15.f) - 1.f;
}

// ------------- BN0 + q16 + im2col -> split bf16 rows -------------------------
__global__ void im2col_kernel(const float* __restrict__ x,
                              const float* __restrict__ bg, const float* __restrict__ bb,
                              const float* __restrict__ bm, const float* __restrict__ bv) {
    int m = blockIdx.x * 256 + threadIdx.x;
    int k = blockIdx.y;
    int c = k >> 2;
    int dy = (k >> 1) & 1, dx = k & 1;
    int b = m / HWOUT, s = m - b * HWOUT;
    int oh = s / HOUT, ow = s - oh * HOUT;
    float v    = x[(((size_t)b * CIN + c) * 56 + oh * 2 + dy) * 56 + ow * 2 + dx];
    float inv  = bg[c] / sqrtf(bv[c] + EPS_BN);
    float bias = bb[c] - bm[c] * inv;
    float y = fminf(fmaxf(v * inv + bias, 0.f), 1.f);
    y = rintf(y * 65535.f) / 65535.f;
    __nv_bfloat16 h = __float2bfloat16(y);
    g_A[(size_t)(2 * k) * MPIX + m]     = h;
    g_A[(size_t)(2 * k + 1) * MPIX + m] = __float2bfloat16(y - __bfloat162float(h));
}

// ------------- tensor-core GEMM, 4-stage cp.async pipeline -------------------
// C[m][n] = (1/15) * sum_{k'} A[k'][m] * B[k'][n],  Kp = k' rows
// MODE 0: write fp32 NCHW        (conv1)
// MODE 1: relu -> split bf16 [2n][M] (expand)
// MODE 2: +resid NCHW, clip, q4 -> fp32 NCHW (project)
#define BM 128
#define BN 128
#define BK 32
#define LDS 136     // bf16 elems; 272B row stride, 16B-aligned, ldmatrix conflict-free
#define STAGES 4
#define MAT_BYTES (BK * LDS * 2)          // 8704 B per matrix per stage
#define STG_BYTES (2 * MAT_BYTES)         // A + B
#define SM_GEMM (STAGES * STG_BYTES)      // 69632 B

template<int MODE>
__global__ void __launch_bounds__(256)
mma_gemm(const __nv_bfloat16* __restrict__ A, const __nv_bfloat16* __restrict__ B,
         int Kp, int N, float* __restrict__ outf, __nv_bfloat16* __restrict__ outp,
         const float* __restrict__ resid) {
    extern __shared__ char smem[];
    const int tid = threadIdx.x;
    const int lane = tid & 31, wid = tid >> 5;
    const int m0b = blockIdx.x * BM, n0b = blockIdx.y * BN;
    const int wm = (wid & 1) * 64;
    const int wn = (wid >> 1) * 32;

    float acc[4][4][4];
    #pragma unroll
    for (int t = 0; t < 4; t++)
        #pragma unroll
        for (int u = 0; u < 4; u++)
            #pragma unroll
            for (int e = 0; e < 4; e++) acc[t][u][e] = 0.f;

    // global->shared mapping: each thread two 16B chunks per tile per matrix
    const int r0 = tid >> 4;          // rows 0..15, +16
    const int c0 = (tid & 15) * 8;    // bf16 col

    const uint32_t sbase = (uint32_t)__cvta_generic_to_shared(smem);
    const uint32_t st_off = (r0 * LDS + c0) * 2;

    // ldmatrix per-thread addresses
    const int g = lane >> 3, r = lane & 7;
    const int a_row0 = ((g >> 1) << 3) + r;
    const int a_col  = wm + ((g & 1) << 3);
    const int b_row0 = ((g & 1) << 3) + r;
    const int b_col0 = wn + ((g >> 1) << 3);

    const int iters = Kp / BK;

    auto load_tile = [&](int it) {
        if (it < iters) {
            const int kb = it * BK;
            const uint32_t sa = sbase + (it % STAGES) * STG_BYTES + st_off;
            const uint32_t sbm = sa + MAT_BYTES;
            const __nv_bfloat16* ag = A + (size_t)(kb + r0) * MPIX + m0b + c0;
            const __nv_bfloat16* bg = B + (size_t)(kb + r0) * N + n0b + c0;
            cp16(sa, ag);
            cp16(sa + 16 * LDS * 2, ag + (size_t)16 * MPIX);
            cp16(sbm, bg);
            cp16(sbm + 16 * LDS * 2, bg + (size_t)16 * N);
        }
        CP_COMMIT();   // always commit (possibly empty) to keep group count fixed
    };

    load_tile(0);
    load_tile(1);
    load_tile(2);

    for (int it = 0; it < iters; ++it) {
        asm volatile("cp.async.wait_group 2;\n");
        __syncthreads();
        load_tile(it + 3);   // overwrites slot of tile it-1 (compute done last iter)

        const uint32_t ab = sbase + (it % STAGES) * STG_BYTES;
        const uint32_t bb = ab + MAT_BYTES;
        #pragma unroll
        for (int h = 0; h < 2; ++h) {
            uint32_t af[4][4];
            #pragma unroll
            for (int t = 0; t < 4; ++t)
                ldmx4t(af[t][0], af[t][1], af[t][2], af[t][3],
                       ab + ((a_row0 + h * 16) * LDS + a_col + t * 16) * 2);
            uint32_t bfr[2][4];
            #pragma unroll
            for (int pq = 0; pq < 2; ++pq)
                ldmx4t(bfr[pq][0], bfr[pq][1], bfr[pq][2], bfr[pq][3],
                       bb + ((b_row0 + h * 16) * LDS + b_col0 + pq * 16) * 2);
            #pragma unroll
            for (int t = 0; t < 4; ++t)
                #pragma unroll
                for (int u = 0; u < 4; ++u)
                    mma16816(acc[t][u], af[t],
                             bfr[u >> 1][(u & 1) * 2], bfr[u >> 1][(u & 1) * 2 + 1]);
        }
    }

    // epilogue
    const float SC = 1.f / 15.f;
    const int row_ = lane >> 2, col_ = (lane & 3) * 2;
    #pragma unroll
    for (int t = 0; t < 4; ++t) {
        #pragma unroll
        for (int u = 0; u < 4; ++u) {
            #pragma unroll
            for (int e = 0; e < 4; ++e) {
                int m = m0b + wm + t * 16 + row_ + ((e >> 1) ? 8 : 0);
                int n = n0b + wn + u * 8 + col_ + (e & 1);
                float v = acc[t][u][e] * SC;
                if (MODE == 0) {
                    int b = m / HWOUT, s = m - b * HWOUT;
                    outf[((size_t)b * COUT + n) * HWOUT + s] = v;
                } else if (MODE == 1) {
                    float vr = fmaxf(v, 0.f);
                    __nv_bfloat16 h = __float2bfloat16(vr);
                    outp[(size_t)(2 * n) * MPIX + m] = h;
                    outp[(size_t)(2 * n + 1) * MPIX + m] =
                        __float2bfloat16(vr - __bfloat162float(h));
                } else {
                    int b = m / HWOUT, s = m - b * HWOUT;
                    size_t idx = ((size_t)b * COUT + n) * HWOUT + s;
                    v += resid[idx];
                    v = fminf(fmaxf(v, 0.f), 1.f);
                    outf[idx] = rintf(v * 15.f) * SC;
                }
            }
        }
    }
}

// ------------- depthwise 7x7 + BN1 -> split bf16 -----------------------------
__global__ void dwconv_kernel(const float* __restrict__ bg, const float* __restrict__ bb,
                              const float* __restrict__ bm, const float* __restrict__ bv) {
    __shared__ float tile[34 * 34];
    __shared__ float w[49];
    int bc = blockIdx.x;
    int c = bc & (COUT - 1);
    int b = bc >> 8;
    const float* plane = g_t0 + (size_t)bc * HWOUT;
    int tid = threadIdx.x;
    for (int idx = tid; idx < 34 * 34; idx += 256) {
        int rr = idx / 34, cc = idx - rr * 34;
        int ih = rr - 3, iw = cc - 3;
        tile[idx] = (ih >= 0 && ih < HOUT && iw >= 0 && iw < HOUT)
                        ? plane[ih * HOUT + iw] : 0.f;
    }
    if (tid < 49) w[tid] = g_W1f[c * 49 + tid];
    __syncthreads();
    float inv  = bg[c] / sqrtf(bv[c] + EPS_BN);
    float bias = bb[c] - bm[c] * inv;
    for (int s = tid; s < HWOUT; s += 256) {
        int oh = s / HOUT, ow = s - oh * HOUT;
        float sum = 0.f;
        #pragma unroll
        for (int i = 0; i < 7; i++)
            #pragma unroll
            for (int j = 0; j < 7; j++)
                sum = fmaf(tile[(oh + i) * 34 + ow + j], w[i * 7 + j], sum);
        float y = sum * inv + bias;
        __nv_bfloat16 h = __float2bfloat16(y);
        int m = b * HWOUT + s;
        g_t1[(size_t)(2 * c) * MPIX + m]     = h;
        g_t1[(size_t)(2 * c + 1) * MPIX + m] = __float2bfloat16(y - __bfloat162float(h));
    }
}

// ------------- launch --------------------------------------------------------
extern "C" void kernel_launch(void* const* d_in, const int* in_sizes, int n_in,
                              void* d_out, int out_size) {
    const float* x     = (const float*)d_in[0];
    const float* bn0_g = (const float*)d_in[1];
    const float* bn0_b = (const float*)d_in[2];
    const float* bn0_m = (const float*)d_in[3];
    const float* bn0_v = (const float*)d_in[4];
    const float* Wd    = (const float*)d_in[5];
    const float* W1    = (const float*)d_in[6];
    const float* bn1_g = (const float*)d_in[7];
    const float* bn1_b = (const float*)d_in[8];
    const float* bn1_m = (const float*)d_in[9];
    const float* bn1_v = (const float*)d_in[10];
    const float* W2    = (const float*)d_in[11];
    const float* W3    = (const float*)d_in[12];
    float* out = (float*)d_out;

    void *pA, *pT0, *pT1, *pT2, *pWd, *pW2, *pW3;
    cudaGetSymbolAddress(&pA,  g_A);
    cudaGetSymbolAddress(&pT0, g_t0);
    cudaGetSymbolAddress(&pT1, g_t1);
    cudaGetSymbolAddress(&pT2, g_t2);
    cudaGetSymbolAddress(&pWd, g_Wd);
    cudaGetSymbolAddress(&pW2, g_W2);
    cudaGetSymbolAddress(&pW3, g_W3);

    cudaFuncSetAttribute(mma_gemm<0>, cudaFuncAttributeMaxDynamicSharedMemorySize, SM_GEMM);
    cudaFuncSetAttribute(mma_gemm<1>, cudaFuncAttributeMaxDynamicSharedMemorySize, SM_GEMM);
    cudaFuncSetAttribute(mma_gemm<2>, cudaFuncAttributeMaxDynamicSharedMemorySize, SM_GEMM);

    // weight quantization (fused launches)
    init_max_kernel<<<1, 32>>>();
    max4_kernel<<<dim3(64, 4), 256>>>(Wd, W1, W2, W3);
    quantW_all<<<dim3(1024, 3), 256>>>(Wd, W2, W3);
    quantW_dw_kernel<<<(COUT * 49 + 255) / 256, 256>>>(W1);

    // BN0 + q16 + im2col (split bf16)
    im2col_kernel<<<dim3(98, KL1), 256>>>(x, bn0_g, bn0_b, bn0_m, bn0_v);

    // conv1: M=25088, N=256, Kp=1024
    mma_gemm<0><<<dim3(MPIX / BM, COUT / BN), 256, SM_GEMM>>>(
        (const __nv_bfloat16*)pA, (const __nv_bfloat16*)pWd, 2 * KL1, COUT,
        (float*)pT0, nullptr, nullptr);

    // depthwise + BN1
    dwconv_kernel<<<BATCH * COUT, 256>>>(bn1_g, bn1_b, bn1_m, bn1_v);

    // expand: N=1024, Kp=512
    mma_gemm<1><<<dim3(MPIX / BM, CEXP / BN), 256, SM_GEMM>>>(
        (const __nv_bfloat16*)pT1, (const __nv_bfloat16*)pW2, 2 * COUT, CEXP,
        nullptr, (__nv_bfloat16*)pT2, nullptr);

    // project: N=256, Kp=2048, + residual + q4
    mma_gemm<2><<<dim3(MPIX / BM, COUT / BN), 256, SM_GEMM>>>(
        (const __nv_bfloat16*)pT2, (const __nv_bfloat16*)pW3, 2 * CEXP, COUT,
        out, nullptr, (const float*)pT0);
}